// round 14
// baseline (speedup 1.0000x reference)
#include <cuda_runtime.h>
#include <cuda_fp16.h>
#include <cstdint>

#define NQ   9216
#define CIN  128
#define CPL  256
#define BATCH 2

// ---------------- scratch (static device allocations, no cudaMalloc) ----------
__device__ uint32_t g_qh[BATCH*64*NQ];        // half2 (c,c+8 of 16-block), [b][p][n]
__device__ uint32_t g_kh[BATCH*64*NQ];        // same pairing as Q
__device__ uint32_t g_vh[BATCH*(NQ/2)*CIN];   // half2 (n,n+1) pairs, [b][npair][c]
__device__ uint32_t g_att[BATCH*64*NQ];       // attention out, half2 (c,c+1), [b][p][n]
__device__ uint32_t g_xh[BATCH*128*NQ];       // x packed, half2 (c,c+1), [b][p][n]
__device__ uint32_t g_bn1h[BATCH*128*NQ];     // bn1 packed, half2 (c,c+1)
__device__ float    g_c1[BATCH*CPL*NQ];
__device__ uint32_t g_wqkv[384*128];          // rows 0-127 Wq(scaled),128-255 Wk,256-383 Wv
__device__ uint32_t g_wc1[256*64];
__device__ uint32_t g_wout[256*256];
__device__ float2   g_st1[CPL];
__device__ float2   g_st2[CPL];

__device__ __forceinline__ void cpa16(uint32_t dst, const void* src) {
    asm volatile("cp.async.cg.shared.global [%0], [%1], 16;" :: "r"(dst), "l"(src));
}
__device__ __forceinline__ uint32_t h2u(__half2 h) { return *(uint32_t*)&h; }
__device__ __forceinline__ void mma_h(float* c,
    uint32_t a0, uint32_t a1, uint32_t a2, uint32_t a3, uint32_t b0, uint32_t b1) {
    asm volatile("mma.sync.aligned.m16n8k16.row.col.f32.f16.f16.f32 "
                 "{%0,%1,%2,%3}, {%4,%5,%6,%7}, {%8,%9}, {%0,%1,%2,%3};"
                 : "+f"(c[0]), "+f"(c[1]), "+f"(c[2]), "+f"(c[3])
                 : "r"(a0), "r"(a1), "r"(a2), "r"(a3), "r"(b0), "r"(b1));
}

// ---------------------------------------------------------------------------
// Packing kernels
// ---------------------------------------------------------------------------
__global__ void pack_w_kernel(const float* __restrict__ Wk, const float* __restrict__ Wv,
                              const float* __restrict__ Wq, const float* __restrict__ Wc1,
                              const float* __restrict__ Wout)
{
    int idx = blockIdx.x * 256 + threadIdx.x;
    if (idx < 384*128) {
        int r = idx >> 7, kp = idx & 127;
        const float* src; float s = 1.f;
        if (r < 128)      { src = Wq + (size_t)r*256;
                            s = 0.08838834764831845f * 1.4426950408889634f; }
        else if (r < 256) { src = Wk + (size_t)(r-128)*256; }
        else              { src = Wv + (size_t)(r-256)*256; }
        g_wqkv[idx] = h2u(__floats2half2_rn(src[2*kp]*s, src[2*kp+1]*s));
    } else if (idx < 384*128 + 256*64) {
        int i = idx - 384*128; int r = i >> 6, kp = i & 63;
        g_wc1[i] = h2u(__floats2half2_rn(Wc1[(size_t)r*128 + 2*kp],
                                         Wc1[(size_t)r*128 + 2*kp + 1]));
    } else if (idx < 384*128 + 256*64 + 256*256) {
        int i = idx - (384*128 + 256*64); int r = i >> 8, kp = i & 255;
        g_wout[i] = h2u(__floats2half2_rn(Wout[(size_t)r*512 + 2*kp],
                                          Wout[(size_t)r*512 + 2*kp + 1]));
    }
}

__global__ void pack_x_kernel(const float* __restrict__ x)
{
    int idx = blockIdx.x * 256 + threadIdx.x;    // BATCH*128*NQ/4 threads
    int n4 = (idx % (NQ/4)) * 4;
    int p  = (idx / (NQ/4)) % 128;
    int b  = idx / (128*(NQ/4));
    const float* r0 = x + ((size_t)b*256 + 2*p) * NQ + n4;
    const float* r1 = r0 + NQ;
    float4 v0 = *(const float4*)r0, v1 = *(const float4*)r1;
    uint4 o;
    o.x = h2u(__floats2half2_rn(v0.x, v1.x));
    o.y = h2u(__floats2half2_rn(v0.y, v1.y));
    o.z = h2u(__floats2half2_rn(v0.z, v1.z));
    o.w = h2u(__floats2half2_rn(v0.w, v1.w));
    *(uint4*)&g_xh[(size_t)b*128*NQ + (size_t)p*NQ + n4] = o;
}

// ---------------------------------------------------------------------------
// fp16 tensor-core GEMM: C[m][n] = sum_k W[m][k] * X[k][n]
// ---------------------------------------------------------------------------
#define XSTR 264
#define WSTR 20

__global__ void __launch_bounds__(256) gemm_h_kernel(
    const uint32_t* __restrict__ Wh,
    const uint32_t* __restrict__ B1,
    const uint32_t* __restrict__ B2,
    float* __restrict__ Cf,
    int K, int K1, int mode)
{
    __shared__ uint32_t Xs[2][16*XSTR];
    __shared__ uint32_t Ws[2][64*WSTR];
    const uint32_t xsb = (uint32_t)__cvta_generic_to_shared(&Xs[0][0]);
    const uint32_t wsb = (uint32_t)__cvta_generic_to_shared(&Ws[0][0]);

    const int b = blockIdx.z;
    const int n0 = blockIdx.x * 256;
    const int y = blockIdx.y;
    const int m0 = y * 64;
    const int tid = threadIdx.x;
    const int lane = tid & 31, w = tid >> 5;
    const int mw = w & 3, nw = w >> 2;
    const int g = lane >> 2, t = lane & 3;
    const int Kh = K >> 1, K1h = K1 >> 1;
    const uint32_t* B1b = B1 + (size_t)b * K1h * NQ;
    const uint32_t* B2b = B2 ? (B2 + (size_t)b * (Kh - K1h) * NQ) : nullptr;
    const int nchunk = Kh / 16;

    {
        const uint32_t* src = B1b + n0;
        #pragma unroll
        for (int j = 0; j < 4; j++) {
            int idx = tid + j * 256;
            int r = idx >> 6, cu = (idx & 63) * 4;
            cpa16(xsb + (uint32_t)(r*XSTR + cu) * 4, src + (size_t)r * NQ + cu);
        }
        int rw = tid >> 2, cw = (tid & 3) * 4;
        cpa16(wsb + (uint32_t)(rw*WSTR + cw) * 4, Wh + (size_t)(m0 + rw) * Kh + cw);
    }
    asm volatile("cp.async.commit_group;");

    float acc[16][4];
    #pragma unroll
    for (int u = 0; u < 16; u++) { acc[u][0]=0; acc[u][1]=0; acc[u][2]=0; acc[u][3]=0; }

    for (int ch = 0; ch < nchunk; ch++) {
        const int buf = ch & 1;
        if (ch + 1 < nchunk) {
            int kp0 = (ch + 1) * 16;
            const uint32_t* src = (kp0 < K1h) ? (B1b + (size_t)kp0 * NQ + n0)
                                              : (B2b + (size_t)(kp0 - K1h) * NQ + n0);
            #pragma unroll
            for (int j = 0; j < 4; j++) {
                int idx = tid + j * 256;
                int r = idx >> 6, cu = (idx & 63) * 4;
                cpa16(xsb + (uint32_t)((buf^1)*16*XSTR + r*XSTR + cu) * 4,
                      src + (size_t)r * NQ + cu);
            }
            int rw = tid >> 2, cw = (tid & 3) * 4;
            cpa16(wsb + (uint32_t)((buf^1)*64*WSTR + rw*WSTR + cw) * 4,
                  Wh + (size_t)(m0 + rw) * Kh + kp0 + cw);
        }
        asm volatile("cp.async.commit_group;");
        asm volatile("cp.async.wait_group 1;");
        __syncthreads();

        const uint32_t* Xb = &Xs[buf][0];
        const uint32_t* Wb = &Ws[buf][0];
        #pragma unroll
        for (int j = 0; j < 2; j++) {
            uint32_t a0 = Wb[(mw*16+g)*WSTR   + 8*j + t];
            uint32_t a1 = Wb[(mw*16+g+8)*WSTR + 8*j + t];
            uint32_t a2 = Wb[(mw*16+g)*WSTR   + 8*j + 4 + t];
            uint32_t a3 = Wb[(mw*16+g+8)*WSTR + 8*j + 4 + t];
            #pragma unroll
            for (int u = 0; u < 16; u++) {
                uint32_t b0 = Xb[(8*j+t)*XSTR   + nw*128 + 8*u + g];
                uint32_t b1 = Xb[(8*j+4+t)*XSTR + nw*128 + 8*u + g];
                mma_h(acc[u], a0, a1, a2, a3, b0, b1);
            }
        }
        __syncthreads();
    }

    const int nb = n0 + nw*128 + 2*t;
    if (mode == 0) {
        float* Cb = Cf + ((size_t)b*256 + m0 + mw*16 + g) * NQ + nb;
        #pragma unroll
        for (int u = 0; u < 16; u++) {
            *(float2*)&Cb[8*u] = make_float2(acc[u][0], acc[u][1]);
            *(float2*)&Cb[(size_t)8*NQ + 8*u] = make_float2(acc[u][2], acc[u][3]);
        }
    } else {
        if (y < 2) {           // Q -> g_qh, pairs (c, c+8)
            uint32_t* dst = g_qh + (size_t)b*64*NQ + (size_t)(8*(y*4+mw)+g)*NQ + nb;
            #pragma unroll
            for (int u = 0; u < 16; u++) {
                uint2 v;
                v.x = h2u(__floats2half2_rn(acc[u][0], acc[u][2]));
                v.y = h2u(__floats2half2_rn(acc[u][1], acc[u][3]));
                *(uint2*)&dst[8*u] = v;
            }
        } else if (y < 4) {    // K -> g_kh
            uint32_t* dst = g_kh + (size_t)b*64*NQ + (size_t)(8*((y-2)*4+mw)+g)*NQ + nb;
            #pragma unroll
            for (int u = 0; u < 16; u++) {
                uint2 v;
                v.x = h2u(__floats2half2_rn(acc[u][0], acc[u][2]));
                v.y = h2u(__floats2half2_rn(acc[u][1], acc[u][3]));
                *(uint2*)&dst[8*u] = v;
            }
        } else {               // V -> g_vh, pairs (n, n+1)
            uint32_t* dst = g_vh + (size_t)b*(NQ/2)*CIN;
            int c = (y-4)*64 + mw*16 + g;
            int npb = (n0 + nw*128)/2 + t;
            #pragma unroll
            for (int u = 0; u < 16; u++) {
                int np = npb + 4*u;
                dst[(size_t)np*CIN + c]     = h2u(__floats2half2_rn(acc[u][0], acc[u][1]));
                dst[(size_t)np*CIN + c + 8] = h2u(__floats2half2_rn(acc[u][2], acc[u][3]));
            }
        }
    }
}

// ---------------------------------------------------------------------------
// Flash attention, fp16 m16n8k16, no-rescale softmax, KEY-SPLIT warps:
// CTA = 64 queries, 256 threads, warp (qw 0..3, kw 0..1): 16 queries x the
// kw-half (32 keys) of each 64-key tile. Additive O/l merged once at end.
// K/V double-buffered, round-9 loop order (S -> softmax -> PV).
// ---------------------------------------------------------------------------
#define KSTH 72
#define VSTH 136
#define KWRD (64*KSTH)          // 4608 u32 per K buffer
#define VWRD (32*VSTH)          // 4352 u32 per V buffer
#define FSMEM ((2*KWRD + 2*VWRD) * 4)   // 71680 bytes

__global__ void __launch_bounds__(256, 1) flash_h_kernel()
{
    extern __shared__ float sm[];
    uint32_t* smu = (uint32_t*)sm;
    const uint32_t smb = (uint32_t)__cvta_generic_to_shared(sm);

    const int b  = blockIdx.y;
    const int q0 = blockIdx.x * 64;
    const int tid  = threadIdx.x;
    const int lane = tid & 31, w = tid >> 5;       // w in 0..7
    const int qw = w & 3, kw = w >> 2;
    const int g = lane >> 2, t = lane & 3;

    const uint32_t* qhb = g_qh + (size_t)b * 64 * NQ;
    const uint32_t* khb = g_kh + (size_t)b * 64 * NQ;
    const uint32_t* vhb = g_vh + (size_t)b * (NQ/2) * CIN;

    // ---- stage Q (64 rows x 64 u32, stride KSTH; overlays K buffer 0) ----
    #pragma unroll
    for (int j = 0; j < 4; j++) {
        int idx = tid + j * 256;
        int p = idx >> 4, o4 = (idx & 15) * 4;
        cpa16(smb + (uint32_t)(p * KSTH + o4) * 4, qhb + (size_t)p * NQ + q0 + o4);
    }
    asm volatile("cp.async.commit_group;");
    asm volatile("cp.async.wait_group 0;");
    __syncthreads();

    const int ql = 16 * qw + g;
    uint32_t qa[8][4];
    #pragma unroll
    for (int s = 0; s < 8; s++) {
        qa[s][0] = smu[(8*s + t)     * KSTH + ql];
        qa[s][1] = smu[(8*s + t)     * KSTH + ql + 8];
        qa[s][2] = smu[(8*s + 4 + t) * KSTH + ql];
        qa[s][3] = smu[(8*s + 4 + t) * KSTH + ql + 8];
    }
    __syncthreads();   // Q region now reusable as K buffers

    // ---- prologue: tile 0 K/V ----
    #pragma unroll
    for (int j = 0; j < 4; j++) {
        int idx = tid + j * 256;
        int r = idx >> 4, ch = (idx & 15) * 4;
        cpa16(smb + (uint32_t)(r * KSTH + ch) * 4, khb + (size_t)r * NQ + ch);
    }
    #pragma unroll
    for (int j = 0; j < 4; j++) {
        int idx = tid + j * 256;
        int r = idx >> 5, ch = (idx & 31) * 4;
        cpa16(smb + (uint32_t)(2*KWRD + r * VSTH + ch) * 4, vhb + (size_t)r * CIN + ch);
    }
    asm volatile("cp.async.commit_group;");

    float o_[16][4];
    #pragma unroll
    for (int n = 0; n < 16; n++) { o_[n][0]=0; o_[n][1]=0; o_[n][2]=0; o_[n][3]=0; }
    float l0 = 0.f, l1 = 0.f;

    for (int kt = 0; kt < NQ/64; kt++) {
        const int cb = kt & 1, nb = cb ^ 1;
        if (kt + 1 < NQ/64) {
            const int k0n  = (kt + 1) * 64;
            const int kp0n = (kt + 1) * 32;
            #pragma unroll
            for (int j = 0; j < 4; j++) {
                int idx = tid + j * 256;
                int r = idx >> 4, ch = (idx & 15) * 4;
                cpa16(smb + (uint32_t)(nb*KWRD + r * KSTH + ch) * 4,
                      khb + (size_t)r * NQ + k0n + ch);
            }
            #pragma unroll
            for (int j = 0; j < 4; j++) {
                int idx = tid + j * 256;
                int r = idx >> 5, ch = (idx & 31) * 4;
                cpa16(smb + (uint32_t)(2*KWRD + nb*VWRD + r * VSTH + ch) * 4,
                      vhb + (size_t)(kp0n + r) * CIN + ch);
            }
        }
        asm volatile("cp.async.commit_group;");
        asm volatile("cp.async.wait_group 1;");
        __syncthreads();

        const uint32_t* Kp = smu + cb * KWRD;
        const uint32_t* Vp = smu + 2*KWRD + cb * VWRD;

        // ---- S = Q^T K (16q x 32k slice: keys 32*kw .. 32*kw+31) ----
        float sc[4][4];
        #pragma unroll
        for (int u = 0; u < 4; u++) { sc[u][0]=0; sc[u][1]=0; sc[u][2]=0; sc[u][3]=0; }
        #pragma unroll
        for (int s = 0; s < 8; s++) {
            const uint32_t* kr0 = Kp + (8*s + t) * KSTH + 32*kw + g;
            const uint32_t* kr1 = kr0 + 4 * KSTH;
            #pragma unroll
            for (int u = 0; u < 4; u++)
                mma_h(sc[u], qa[s][0], qa[s][1], qa[s][2], qa[s][3],
                      kr0[8*u], kr1[8*u]);
        }

        // ---- no-rescale softmax: P = 2^s (f16x2 exp2), l partials ----
        uint32_t pb[4][2];
        #pragma unroll
        for (int u = 0; u < 4; u++) {
            __half2 p01 = h2exp2(__floats2half2_rn(sc[u][0], sc[u][1]));
            __half2 p23 = h2exp2(__floats2half2_rn(sc[u][2], sc[u][3]));
            pb[u][0] = h2u(p01); pb[u][1] = h2u(p23);
            float2 f0 = __half22float2(p01), f1 = __half22float2(p23);
            l0 += f0.x + f0.y; l1 += f1.x + f1.y;
        }

        // ---- O += P V^T over this warp's 32 keys ----
        #pragma unroll
        for (int nb2 = 0; nb2 < 16; nb2++) {
            #pragma unroll
            for (int ss = 0; ss < 2; ss++) {
                uint32_t b0 = Vp[(16*kw + 8*ss + t)     * VSTH + 8*nb2 + g];
                uint32_t b1 = Vp[(16*kw + 8*ss + 4 + t) * VSTH + 8*nb2 + g];
                mma_h(o_[nb2], pb[2*ss][0], pb[2*ss][1], pb[2*ss+1][0], pb[2*ss+1][1],
                      b0, b1);
            }
        }
        __syncthreads();   // all warps done reading K[cb], V[cb]
    }

    // ---- epilogue: quad-reduce l, merge kw halves via smem, store ----
    l0 += __shfl_xor_sync(0xffffffffu, l0, 1);
    l0 += __shfl_xor_sync(0xffffffffu, l0, 2);
    l1 += __shfl_xor_sync(0xffffffffu, l1, 1);
    l1 += __shfl_xor_sync(0xffffffffu, l1, 2);

    __syncthreads();                     // safe to overwrite K region
    float2* Osm = (float2*)sm;           // [64 rows][64 float2] = 32 KB
    float*  Lsm = sm + 8192;             // [64] l partials from kw=1
    if (kw == 1) {
        #pragma unroll
        for (int nb2 = 0; nb2 < 16; nb2++) {
            int p = 4*nb2 + t;
            Osm[(16*qw + g    ) * 64 + p] = make_float2(o_[nb2][0], o_[nb2][1]);
            Osm[(16*qw + g + 8) * 64 + p] = make_float2(o_[nb2][2], o_[nb2][3]);
        }
        if (t == 0) { Lsm[16*qw + g] = l0; Lsm[16*qw + g + 8] = l1; }
    }
    __syncthreads();
    if (kw == 0) {
        const float i0 = 1.f / (l0 + Lsm[16*qw + g]);
        const float i1 = 1.f / (l1 + Lsm[16*qw + g + 8]);
        uint32_t* op = g_att + (size_t)b * 64 * NQ;
        const int qA = q0 + 16*qw + g, qB = qA + 8;
        #pragma unroll
        for (int nb2 = 0; nb2 < 16; nb2++) {
            int p = 4*nb2 + t;
            float2 oa = Osm[(16*qw + g    ) * 64 + p];
            float2 ob = Osm[(16*qw + g + 8) * 64 + p];
            op[(size_t)p * NQ + qA] =
                h2u(__floats2half2_rn((o_[nb2][0] + oa.x)*i0, (o_[nb2][1] + oa.y)*i0));
            op[(size_t)p * NQ + qB] =
                h2u(__floats2half2_rn((o_[nb2][2] + ob.x)*i1, (o_[nb2][3] + ob.y)*i1));
        }
    }
}

// ---------------------------------------------------------------------------
// BN statistics + BN/ReLU epilogues
// ---------------------------------------------------------------------------
__global__ void stats_kernel(const float* __restrict__ buf, float2* __restrict__ st, int C)
{
    const int ch = blockIdx.x, tid = threadIdx.x;
    float s1 = 0.f, s2 = 0.f;
    for (int b = 0; b < BATCH; b++) {
        const float* p = buf + ((size_t)b * C + ch) * NQ;
        for (int n = tid * 4; n < NQ; n += 1024) {
            float4 t = *(const float4*)(p + n);
            s1 += t.x + t.y + t.z + t.w;
            s2 += t.x*t.x + t.y*t.y + t.z*t.z + t.w*t.w;
        }
    }
    __shared__ float sh1[256], sh2[256];
    sh1[tid] = s1; sh2[tid] = s2;
    __syncthreads();
    for (int o = 128; o; o >>= 1) {
        if (tid < o) { sh1[tid] += sh1[tid + o]; sh2[tid] += sh2[tid + o]; }
        __syncthreads();
    }
    if (tid == 0) {
        float invn = 1.f / (float)(BATCH * NQ);
        float mean = sh1[0] * invn;
        float var  = sh2[0] * invn - mean * mean;
        st[ch] = make_float2(mean, rsqrtf(var + 1e-5f));
    }
}

// BN+ReLU on g_c1, output packed half2 (c,c+1) pairs into g_bn1h
__global__ void bn_relu_pack_kernel(const float* __restrict__ in,
                                    const float2* __restrict__ st,
                                    const float* __restrict__ gamma,
                                    const float* __restrict__ beta)
{
    int idx = blockIdx.x * 256 + threadIdx.x;     // BATCH*128*NQ/4
    int n4 = (idx % (NQ/4)) * 4;
    int p  = (idx / (NQ/4)) % 128;
    int b  = idx / (128*(NQ/4));
    int c0 = 2*p, c1 = 2*p + 1;
    float2 sA = st[c0], sB = st[c1];
    float gA = gamma[c0] * sA.y, bA = beta[c0] - sA.x * gA;
    float gB = gamma[c1] * sB.y, bB = beta[c1] - sB.x * gB;
    const float* r0 = in + ((size_t)b*256 + c0) * NQ + n4;
    const float* r1 = r0 + NQ;
    float4 v0 = *(const float4*)r0, v1 = *(const float4*)r1;
    v0.x = fmaxf(v0.x*gA + bA, 0.f); v0.y = fmaxf(v0.y*gA + bA, 0.f);
    v0.z = fmaxf(v0.z*gA + bA, 0.f); v0.w = fmaxf(v0.w*gA + bA, 0.f);
    v1.x = fmaxf(v1.x*gB + bB, 0.f); v1.y = fmaxf(v1.y*gB + bB, 0.f);
    v1.z = fmaxf(v1.z*gB + bB, 0.f); v1.w = fmaxf(v1.w*gB + bB, 0.f);
    uint4 o;
    o.x = h2u(__floats2half2_rn(v0.x, v1.x));
    o.y = h2u(__floats2half2_rn(v0.y, v1.y));
    o.z = h2u(__floats2half2_rn(v0.z, v1.z));
    o.w = h2u(__floats2half2_rn(v0.w, v1.w));
    *(uint4*)&g_bn1h[(size_t)b*128*NQ + (size_t)p*NQ + n4] = o;
}

__global__ void bn_relu_kernel(const float* __restrict__ in, float* __restrict__ out,
                               const float2* __restrict__ st,
                               const float* __restrict__ gamma,
                               const float* __restrict__ beta, int C)
{
    size_t idx = (size_t)blockIdx.x * blockDim.x + threadIdx.x;
    size_t fi = idx * 4;
    int ch = (int)((fi / NQ) % C);
    float2 s = st[ch];
    float g  = gamma[ch] * s.y;
    float bb = beta[ch] - s.x * g;
    float4 t = *(const float4*)(in + fi);
    t.x = fmaxf(t.x * g + bb, 0.f);
    t.y = fmaxf(t.y * g + bb, 0.f);
    t.z = fmaxf(t.z * g + bb, 0.f);
    t.w = fmaxf(t.w * g + bb, 0.f);
    *(float4*)(out + fi) = t;
}

// ---------------------------------------------------------------------------
extern "C" void kernel_launch(void* const* d_in, const int* in_sizes, int n_in,
                              void* d_out, int out_size)
{
    const float* x      = (const float*)d_in[0];
    const float* Wk     = (const float*)d_in[1];
    const float* Wv     = (const float*)d_in[2];
    const float* Wq     = (const float*)d_in[3];
    const float* Wc1    = (const float*)d_in[4];
    const float* gamma1 = (const float*)d_in[5];
    const float* beta1  = (const float*)d_in[6];
    const float* Wout   = (const float*)d_in[7];
    const float* gamma2 = (const float*)d_in[8];
    const float* beta2  = (const float*)d_in[9];
    float* out = (float*)d_out;

    void *pwqkv, *pwc1, *pwout, *pxh, *patt, *pbn1h, *pc1, *pst1, *pst2;
    cudaGetSymbolAddress(&pwqkv, g_wqkv);
    cudaGetSymbolAddress(&pwc1,  g_wc1);
    cudaGetSymbolAddress(&pwout, g_wout);
    cudaGetSymbolAddress(&pxh,   g_xh);
    cudaGetSymbolAddress(&patt,  g_att);
    cudaGetSymbolAddress(&pbn1h, g_bn1h);
    cudaGetSymbolAddress(&pc1,   g_c1);
    cudaGetSymbolAddress(&pst1,  g_st1);
    cudaGetSymbolAddress(&pst2,  g_st2);

    // pack weights + x to fp16
    pack_w_kernel<<<512, 256>>>(Wk, Wv, Wq, Wc1, Wout);
    pack_x_kernel<<<BATCH*128*(NQ/4)/256, 256>>>(x);

    // fused QKV projection (tensor cores) -> packed q/k/v
    gemm_h_kernel<<<dim3(NQ/256, 6, BATCH), 256>>>(
        (const uint32_t*)pwqkv, (const uint32_t*)pxh, nullptr, nullptr, 256, 256, 3);

    // flash attention (64q CTAs, 256 threads, key-split warps)
    cudaFuncSetAttribute((const void*)flash_h_kernel,
                         cudaFuncAttributeMaxDynamicSharedMemorySize, FSMEM);
    flash_h_kernel<<<dim3(NQ/64, BATCH), 256, FSMEM>>>();

    // conv1: Wc1 @ att -> g_c1 (fp32), then BN stats + BN/ReLU (packed out)
    gemm_h_kernel<<<dim3(NQ/256, 4, BATCH), 256>>>(
        (const uint32_t*)pwc1, (const uint32_t*)patt, nullptr, (float*)pc1, 128, 128, 0);
    stats_kernel<<<CPL, 256>>>((float*)pc1, (float2*)pst1, CPL);
    bn_relu_pack_kernel<<<BATCH*128*(NQ/4)/256, 256>>>((float*)pc1, (float2*)pst1,
                                                       gamma1, beta1);

    // out conv on concat [xh ; bn1h] -> d_out, then BN stats + BN/ReLU in place
    gemm_h_kernel<<<dim3(NQ/256, 4, BATCH), 256>>>(
        (const uint32_t*)pwout, (const uint32_t*)pxh, (const uint32_t*)pbn1h,
        out, 512, 256, 0);
    stats_kernel<<<CPL, 256>>>(out, (float2*)pst2, CPL);
    bn_relu_kernel<<<(BATCH*CPL*NQ/4)/256, 256>>>(out, out, (float2*)pst2,
                                                  gamma2, beta2, CPL);
}

// round 15
// speedup vs baseline: 1.1071x; 1.1071x over previous
#include <cuda_runtime.h>
#include <cuda_fp16.h>
#include <cstdint>

#define NQ   9216
#define CIN  128
#define CPL  256
#define BATCH 2

// ---------------- scratch (static device allocations, no cudaMalloc) ----------
__device__ uint32_t g_qh[BATCH*64*NQ];        // half2 (c,c+8 of 16-block), [b][p][n]
__device__ uint32_t g_kh[BATCH*64*NQ];        // same pairing as Q
__device__ uint32_t g_vh[BATCH*(NQ/2)*CIN];   // half2 (n,n+1) pairs, [b][npair][c]
__device__ uint32_t g_att[BATCH*64*NQ];       // attention out, half2 (c,c+1), [b][p][n]
__device__ uint32_t g_xh[BATCH*128*NQ];       // x packed, half2 (c,c+1), [b][p][n]
__device__ uint32_t g_bn1h[BATCH*128*NQ];     // bn1 packed, half2 (c,c+1)
__device__ float    g_c1[BATCH*CPL*NQ];
__device__ uint32_t g_wqkv[384*128];          // rows 0-127 Wq(scaled),128-255 Wk,256-383 Wv
__device__ uint32_t g_wc1[256*64];
__device__ uint32_t g_wout[256*256];
__device__ float2   g_st1[CPL];
__device__ float2   g_st2[CPL];

__device__ __forceinline__ void cpa16(uint32_t dst, const void* src) {
    asm volatile("cp.async.cg.shared.global [%0], [%1], 16;" :: "r"(dst), "l"(src));
}
__device__ __forceinline__ uint32_t h2u(__half2 h) { return *(uint32_t*)&h; }
__device__ __forceinline__ void mma_h(float* c,
    uint32_t a0, uint32_t a1, uint32_t a2, uint32_t a3, uint32_t b0, uint32_t b1) {
    asm volatile("mma.sync.aligned.m16n8k16.row.col.f32.f16.f16.f32 "
                 "{%0,%1,%2,%3}, {%4,%5,%6,%7}, {%8,%9}, {%0,%1,%2,%3};"
                 : "+f"(c[0]), "+f"(c[1]), "+f"(c[2]), "+f"(c[3])
                 : "r"(a0), "r"(a1), "r"(a2), "r"(a3), "r"(b0), "r"(b1));
}

// ---------------------------------------------------------------------------
// Packing kernels
// ---------------------------------------------------------------------------
__global__ void pack_w_kernel(const float* __restrict__ Wk, const float* __restrict__ Wv,
                              const float* __restrict__ Wq, const float* __restrict__ Wc1,
                              const float* __restrict__ Wout)
{
    int idx = blockIdx.x * 256 + threadIdx.x;
    if (idx < 384*128) {
        int r = idx >> 7, kp = idx & 127;
        const float* src; float s = 1.f;
        if (r < 128)      { src = Wq + (size_t)r*256;
                            s = 0.08838834764831845f * 1.4426950408889634f; }
        else if (r < 256) { src = Wk + (size_t)(r-128)*256; }
        else              { src = Wv + (size_t)(r-256)*256; }
        g_wqkv[idx] = h2u(__floats2half2_rn(src[2*kp]*s, src[2*kp+1]*s));
    } else if (idx < 384*128 + 256*64) {
        int i = idx - 384*128; int r = i >> 6, kp = i & 63;
        g_wc1[i] = h2u(__floats2half2_rn(Wc1[(size_t)r*128 + 2*kp],
                                         Wc1[(size_t)r*128 + 2*kp + 1]));
    } else if (idx < 384*128 + 256*64 + 256*256) {
        int i = idx - (384*128 + 256*64); int r = i >> 8, kp = i & 255;
        g_wout[i] = h2u(__floats2half2_rn(Wout[(size_t)r*512 + 2*kp],
                                          Wout[(size_t)r*512 + 2*kp + 1]));
    }
}

__global__ void pack_x_kernel(const float* __restrict__ x)
{
    int idx = blockIdx.x * 256 + threadIdx.x;    // BATCH*128*NQ/4 threads
    int n4 = (idx % (NQ/4)) * 4;
    int p  = (idx / (NQ/4)) % 128;
    int b  = idx / (128*(NQ/4));
    const float* r0 = x + ((size_t)b*256 + 2*p) * NQ + n4;
    const float* r1 = r0 + NQ;
    float4 v0 = *(const float4*)r0, v1 = *(const float4*)r1;
    uint4 o;
    o.x = h2u(__floats2half2_rn(v0.x, v1.x));
    o.y = h2u(__floats2half2_rn(v0.y, v1.y));
    o.z = h2u(__floats2half2_rn(v0.z, v1.z));
    o.w = h2u(__floats2half2_rn(v0.w, v1.w));
    *(uint4*)&g_xh[(size_t)b*128*NQ + (size_t)p*NQ + n4] = o;
}

// ---------------------------------------------------------------------------
// fp16 tensor-core GEMM: C[m][n] = sum_k W[m][k] * X[k][n]
// ---------------------------------------------------------------------------
#define XSTR 264
#define WSTR 20

__global__ void __launch_bounds__(256) gemm_h_kernel(
    const uint32_t* __restrict__ Wh,
    const uint32_t* __restrict__ B1,
    const uint32_t* __restrict__ B2,
    float* __restrict__ Cf,
    int K, int K1, int mode)
{
    __shared__ uint32_t Xs[2][16*XSTR];
    __shared__ uint32_t Ws[2][64*WSTR];
    const uint32_t xsb = (uint32_t)__cvta_generic_to_shared(&Xs[0][0]);
    const uint32_t wsb = (uint32_t)__cvta_generic_to_shared(&Ws[0][0]);

    const int b = blockIdx.z;
    const int n0 = blockIdx.x * 256;
    const int y = blockIdx.y;
    const int m0 = y * 64;
    const int tid = threadIdx.x;
    const int lane = tid & 31, w = tid >> 5;
    const int mw = w & 3, nw = w >> 2;
    const int g = lane >> 2, t = lane & 3;
    const int Kh = K >> 1, K1h = K1 >> 1;
    const uint32_t* B1b = B1 + (size_t)b * K1h * NQ;
    const uint32_t* B2b = B2 ? (B2 + (size_t)b * (Kh - K1h) * NQ) : nullptr;
    const int nchunk = Kh / 16;

    {
        const uint32_t* src = B1b + n0;
        #pragma unroll
        for (int j = 0; j < 4; j++) {
            int idx = tid + j * 256;
            int r = idx >> 6, cu = (idx & 63) * 4;
            cpa16(xsb + (uint32_t)(r*XSTR + cu) * 4, src + (size_t)r * NQ + cu);
        }
        int rw = tid >> 2, cw = (tid & 3) * 4;
        cpa16(wsb + (uint32_t)(rw*WSTR + cw) * 4, Wh + (size_t)(m0 + rw) * Kh + cw);
    }
    asm volatile("cp.async.commit_group;");

    float acc[16][4];
    #pragma unroll
    for (int u = 0; u < 16; u++) { acc[u][0]=0; acc[u][1]=0; acc[u][2]=0; acc[u][3]=0; }

    for (int ch = 0; ch < nchunk; ch++) {
        const int buf = ch & 1;
        if (ch + 1 < nchunk) {
            int kp0 = (ch + 1) * 16;
            const uint32_t* src = (kp0 < K1h) ? (B1b + (size_t)kp0 * NQ + n0)
                                              : (B2b + (size_t)(kp0 - K1h) * NQ + n0);
            #pragma unroll
            for (int j = 0; j < 4; j++) {
                int idx = tid + j * 256;
                int r = idx >> 6, cu = (idx & 63) * 4;
                cpa16(xsb + (uint32_t)((buf^1)*16*XSTR + r*XSTR + cu) * 4,
                      src + (size_t)r * NQ + cu);
            }
            int rw = tid >> 2, cw = (tid & 3) * 4;
            cpa16(wsb + (uint32_t)((buf^1)*64*WSTR + rw*WSTR + cw) * 4,
                  Wh + (size_t)(m0 + rw) * Kh + kp0 + cw);
        }
        asm volatile("cp.async.commit_group;");
        asm volatile("cp.async.wait_group 1;");
        __syncthreads();

        const uint32_t* Xb = &Xs[buf][0];
        const uint32_t* Wb = &Ws[buf][0];
        #pragma unroll
        for (int j = 0; j < 2; j++) {
            uint32_t a0 = Wb[(mw*16+g)*WSTR   + 8*j + t];
            uint32_t a1 = Wb[(mw*16+g+8)*WSTR + 8*j + t];
            uint32_t a2 = Wb[(mw*16+g)*WSTR   + 8*j + 4 + t];
            uint32_t a3 = Wb[(mw*16+g+8)*WSTR + 8*j + 4 + t];
            #pragma unroll
            for (int u = 0; u < 16; u++) {
                uint32_t b0 = Xb[(8*j+t)*XSTR   + nw*128 + 8*u + g];
                uint32_t b1 = Xb[(8*j+4+t)*XSTR + nw*128 + 8*u + g];
                mma_h(acc[u], a0, a1, a2, a3, b0, b1);
            }
        }
        __syncthreads();
    }

    const int nb = n0 + nw*128 + 2*t;
    if (mode == 0) {
        float* Cb = Cf + ((size_t)b*256 + m0 + mw*16 + g) * NQ + nb;
        #pragma unroll
        for (int u = 0; u < 16; u++) {
            *(float2*)&Cb[8*u] = make_float2(acc[u][0], acc[u][1]);
            *(float2*)&Cb[(size_t)8*NQ + 8*u] = make_float2(acc[u][2], acc[u][3]);
        }
    } else {
        if (y < 2) {           // Q -> g_qh, pairs (c, c+8)
            uint32_t* dst = g_qh + (size_t)b*64*NQ + (size_t)(8*(y*4+mw)+g)*NQ + nb;
            #pragma unroll
            for (int u = 0; u < 16; u++) {
                uint2 v;
                v.x = h2u(__floats2half2_rn(acc[u][0], acc[u][2]));
                v.y = h2u(__floats2half2_rn(acc[u][1], acc[u][3]));
                *(uint2*)&dst[8*u] = v;
            }
        } else if (y < 4) {    // K -> g_kh
            uint32_t* dst = g_kh + (size_t)b*64*NQ + (size_t)(8*((y-2)*4+mw)+g)*NQ + nb;
            #pragma unroll
            for (int u = 0; u < 16; u++) {
                uint2 v;
                v.x = h2u(__floats2half2_rn(acc[u][0], acc[u][2]));
                v.y = h2u(__floats2half2_rn(acc[u][1], acc[u][3]));
                *(uint2*)&dst[8*u] = v;
            }
        } else {               // V -> g_vh, pairs (n, n+1)
            uint32_t* dst = g_vh + (size_t)b*(NQ/2)*CIN;
            int c = (y-4)*64 + mw*16 + g;
            int npb = (n0 + nw*128)/2 + t;
            #pragma unroll
            for (int u = 0; u < 16; u++) {
                int np = npb + 4*u;
                dst[(size_t)np*CIN + c]     = h2u(__floats2half2_rn(acc[u][0], acc[u][1]));
                dst[(size_t)np*CIN + c + 8] = h2u(__floats2half2_rn(acc[u][2], acc[u][3]));
            }
        }
    }
}

// ---------------------------------------------------------------------------
// Flash attention, fp16 m16n8k16, no-rescale softmax (P = 2^s directly).
// Round-9 structure: CTA 64q x 4 warps, 2 CTAs/SM, K/V double-buffered,
// order S -> pb -> PV -> l (l-accum sunk after PV to shorten the S->PV chain).
// ---------------------------------------------------------------------------
#define KSTH 72
#define VSTH 136
#define KWRD (64*KSTH)
#define VWRD (32*VSTH)
#define FSMEM ((2*KWRD + 2*VWRD) * 4)   // 71680 bytes

__global__ void __launch_bounds__(128, 2) flash_h_kernel()
{
    extern __shared__ float sm[];
    uint32_t* smu = (uint32_t*)sm;
    const uint32_t smb = (uint32_t)__cvta_generic_to_shared(sm);

    const int b  = blockIdx.y;
    const int q0 = blockIdx.x * 64;
    const int tid  = threadIdx.x;
    const int lane = tid & 31, w = tid >> 5;       // w in 0..3
    const int g = lane >> 2, t = lane & 3;

    const uint32_t* qhb = g_qh + (size_t)b * 64 * NQ;
    const uint32_t* khb = g_kh + (size_t)b * 64 * NQ;
    const uint32_t* vhb = g_vh + (size_t)b * (NQ/2) * CIN;

    // ---- stage Q (64 rows x 64 u32, stride KSTH; overlays K buffer 0) ----
    #pragma unroll
    for (int j = 0; j < 8; j++) {
        int idx = tid + j * 128;
        int p = idx >> 4, o4 = (idx & 15) * 4;
        cpa16(smb + (uint32_t)(p * KSTH + o4) * 4, qhb + (size_t)p * NQ + q0 + o4);
    }
    asm volatile("cp.async.commit_group;");
    asm volatile("cp.async.wait_group 0;");
    __syncthreads();

    const int ql = 16 * w + g;
    uint32_t qa[8][4];
    #pragma unroll
    for (int s = 0; s < 8; s++) {
        qa[s][0] = smu[(8*s + t)     * KSTH + ql];
        qa[s][1] = smu[(8*s + t)     * KSTH + ql + 8];
        qa[s][2] = smu[(8*s + 4 + t) * KSTH + ql];
        qa[s][3] = smu[(8*s + 4 + t) * KSTH + ql + 8];
    }
    __syncthreads();   // Q region now reusable as K buffers

    // ---- prologue: tile 0 K/V ----
    #pragma unroll
    for (int j = 0; j < 8; j++) {
        int idx = tid + j * 128;
        int r = idx >> 4, ch = (idx & 15) * 4;
        cpa16(smb + (uint32_t)(r * KSTH + ch) * 4, khb + (size_t)r * NQ + ch);
    }
    #pragma unroll
    for (int j = 0; j < 8; j++) {
        int idx = tid + j * 128;
        int r = idx >> 5, ch = (idx & 31) * 4;
        cpa16(smb + (uint32_t)(2*KWRD + r * VSTH + ch) * 4, vhb + (size_t)r * CIN + ch);
    }
    asm volatile("cp.async.commit_group;");

    float o_[16][4];
    #pragma unroll
    for (int n = 0; n < 16; n++) { o_[n][0]=0; o_[n][1]=0; o_[n][2]=0; o_[n][3]=0; }
    float l0 = 0.f, l1 = 0.f;

    for (int kt = 0; kt < NQ/64; kt++) {
        const int cb = kt & 1, nb = cb ^ 1;
        if (kt + 1 < NQ/64) {
            const int k0n  = (kt + 1) * 64;
            const int kp0n = (kt + 1) * 32;
            #pragma unroll
            for (int j = 0; j < 8; j++) {
                int idx = tid + j * 128;
                int r = idx >> 4, ch = (idx & 15) * 4;
                cpa16(smb + (uint32_t)(nb*KWRD + r * KSTH + ch) * 4,
                      khb + (size_t)r * NQ + k0n + ch);
            }
            #pragma unroll
            for (int j = 0; j < 8; j++) {
                int idx = tid + j * 128;
                int r = idx >> 5, ch = (idx & 31) * 4;
                cpa16(smb + (uint32_t)(2*KWRD + nb*VWRD + r * VSTH + ch) * 4,
                      vhb + (size_t)(kp0n + r) * CIN + ch);
            }
        }
        asm volatile("cp.async.commit_group;");
        asm volatile("cp.async.wait_group 1;");
        __syncthreads();

        const uint32_t* Kp = smu + cb * KWRD;
        const uint32_t* Vp = smu + 2*KWRD + cb * VWRD;

        // ---- S = Q^T K ----
        float sc[8][4];
        #pragma unroll
        for (int u = 0; u < 8; u++) { sc[u][0]=0; sc[u][1]=0; sc[u][2]=0; sc[u][3]=0; }
        #pragma unroll
        for (int s = 0; s < 8; s++) {
            const uint32_t* kr0 = Kp + (8*s + t) * KSTH + g;
            const uint32_t* kr1 = kr0 + 4 * KSTH;
            #pragma unroll
            for (int u = 0; u < 8; u++)
                mma_h(sc[u], qa[s][0], qa[s][1], qa[s][2], qa[s][3],
                      kr0[8*u], kr1[8*u]);
        }

        // ---- pb = 2^sc (shortest chain from S results to PV operands) ----
        uint32_t pb[8][2];
        #pragma unroll
        for (int u = 0; u < 8; u++) {
            pb[u][0] = h2u(h2exp2(__floats2half2_rn(sc[u][0], sc[u][1])));
            pb[u][1] = h2u(h2exp2(__floats2half2_rn(sc[u][2], sc[u][3])));
        }

        // ---- O += P V^T ----
        #pragma unroll
        for (int nb2 = 0; nb2 < 16; nb2++) {
            #pragma unroll
            for (int s = 0; s < 4; s++) {
                uint32_t b0 = Vp[(8*s + t)     * VSTH + 8*nb2 + g];
                uint32_t b1 = Vp[(8*s + 4 + t) * VSTH + 8*nb2 + g];
                mma_h(o_[nb2], pb[2*s][0], pb[2*s][1], pb[2*s+1][0], pb[2*s+1][1],
                      b0, b1);
            }
        }

        // ---- l partials from pb (independent of MMA results; fills gaps) ----
        #pragma unroll
        for (int u = 0; u < 8; u++) {
            float2 f0 = __half22float2(*(__half2*)&pb[u][0]);
            float2 f1 = __half22float2(*(__half2*)&pb[u][1]);
            l0 += f0.x + f0.y; l1 += f1.x + f1.y;
        }

        __syncthreads();   // all warps done reading K[cb], V[cb]
    }

    // ---- epilogue: reduce l across quad, normalize, pack, store ----
    l0 += __shfl_xor_sync(0xffffffffu, l0, 1);
    l0 += __shfl_xor_sync(0xffffffffu, l0, 2);
    l1 += __shfl_xor_sync(0xffffffffu, l1, 1);
    l1 += __shfl_xor_sync(0xffffffffu, l1, 2);
    const float i0 = 1.f / l0, i1 = 1.f / l1;
    uint32_t* op = g_att + (size_t)b * 64 * NQ;
    const int qA = q0 + 16*w + g, qB = qA + 8;
    #pragma unroll
    for (int nb2 = 0; nb2 < 16; nb2++) {
        int p = 4*nb2 + t;
        op[(size_t)p * NQ + qA] = h2u(__floats2half2_rn(o_[nb2][0]*i0, o_[nb2][1]*i0));
        op[(size_t)p * NQ + qB] = h2u(__floats2half2_rn(o_[nb2][2]*i1, o_[nb2][3]*i1));
    }
}

// ---------------------------------------------------------------------------
// BN statistics + BN/ReLU epilogues
// ---------------------------------------------------------------------------
__global__ void stats_kernel(const float* __restrict__ buf, float2* __restrict__ st, int C)
{
    const int ch = blockIdx.x, tid = threadIdx.x;
    float s1 = 0.f, s2 = 0.f;
    for (int b = 0; b < BATCH; b++) {
        const float* p = buf + ((size_t)b * C + ch) * NQ;
        for (int n = tid * 4; n < NQ; n += 1024) {
            float4 t = *(const float4*)(p + n);
            s1 += t.x + t.y + t.z + t.w;
            s2 += t.x*t.x + t.y*t.y + t.z*t.z + t.w*t.w;
        }
    }
    __shared__ float sh1[256], sh2[256];
    sh1[tid] = s1; sh2[tid] = s2;
    __syncthreads();
    for (int o = 128; o; o >>= 1) {
        if (tid < o) { sh1[tid] += sh1[tid + o]; sh2[tid] += sh2[tid + o]; }
        __syncthreads();
    }
    if (tid == 0) {
        float invn = 1.f / (float)(BATCH * NQ);
        float mean = sh1[0] * invn;
        float var  = sh2[0] * invn - mean * mean;
        st[ch] = make_float2(mean, rsqrtf(var + 1e-5f));
    }
}

// BN+ReLU on g_c1, output packed half2 (c,c+1) pairs into g_bn1h
__global__ void bn_relu_pack_kernel(const float* __restrict__ in,
                                    const float2* __restrict__ st,
                                    const float* __restrict__ gamma,
                                    const float* __restrict__ beta)
{
    int idx = blockIdx.x * 256 + threadIdx.x;     // BATCH*128*NQ/4
    int n4 = (idx % (NQ/4)) * 4;
    int p  = (idx / (NQ/4)) % 128;
    int b  = idx / (128*(NQ/4));
    int c0 = 2*p, c1 = 2*p + 1;
    float2 sA = st[c0], sB = st[c1];
    float gA = gamma[c0] * sA.y, bA = beta[c0] - sA.x * gA;
    float gB = gamma[c1] * sB.y, bB = beta[c1] - sB.x * gB;
    const float* r0 = in + ((size_t)b*256 + c0) * NQ + n4;
    const float* r1 = r0 + NQ;
    float4 v0 = *(const float4*)r0, v1 = *(const float4*)r1;
    v0.x = fmaxf(v0.x*gA + bA, 0.f); v0.y = fmaxf(v0.y*gA + bA, 0.f);
    v0.z = fmaxf(v0.z*gA + bA, 0.f); v0.w = fmaxf(v0.w*gA + bA, 0.f);
    v1.x = fmaxf(v1.x*gB + bB, 0.f); v1.y = fmaxf(v1.y*gB + bB, 0.f);
    v1.z = fmaxf(v1.z*gB + bB, 0.f); v1.w = fmaxf(v1.w*gB + bB, 0.f);
    uint4 o;
    o.x = h2u(__floats2half2_rn(v0.x, v1.x));
    o.y = h2u(__floats2half2_rn(v0.y, v1.y));
    o.z = h2u(__floats2half2_rn(v0.z, v1.z));
    o.w = h2u(__floats2half2_rn(v0.w, v1.w));
    *(uint4*)&g_bn1h[(size_t)b*128*NQ + (size_t)p*NQ + n4] = o;
}

__global__ void bn_relu_kernel(const float* __restrict__ in, float* __restrict__ out,
                               const float2* __restrict__ st,
                               const float* __restrict__ gamma,
                               const float* __restrict__ beta, int C)
{
    size_t idx = (size_t)blockIdx.x * blockDim.x + threadIdx.x;
    size_t fi = idx * 4;
    int ch = (int)((fi / NQ) % C);
    float2 s = st[ch];
    float g  = gamma[ch] * s.y;
    float bb = beta[ch] - s.x * g;
    float4 t = *(const float4*)(in + fi);
    t.x = fmaxf(t.x * g + bb, 0.f);
    t.y = fmaxf(t.y * g + bb, 0.f);
    t.z = fmaxf(t.z * g + bb, 0.f);
    t.w = fmaxf(t.w * g + bb, 0.f);
    *(float4*)(out + fi) = t;
}

// ---------------------------------------------------------------------------
extern "C" void kernel_launch(void* const* d_in, const int* in_sizes, int n_in,
                              void* d_out, int out_size)
{
    const float* x      = (const float*)d_in[0];
    const float* Wk     = (const float*)d_in[1];
    const float* Wv     = (const float*)d_in[2];
    const float* Wq     = (const float*)d_in[3];
    const float* Wc1    = (const float*)d_in[4];
    const float* gamma1 = (const float*)d_in[5];
    const float* beta1  = (const float*)d_in[6];
    const float* Wout   = (const float*)d_in[7];
    const float* gamma2 = (const float*)d_in[8];
    const float* beta2  = (const float*)d_in[9];
    float* out = (float*)d_out;

    void *pwqkv, *pwc1, *pwout, *pxh, *patt, *pbn1h, *pc1, *pst1, *pst2;
    cudaGetSymbolAddress(&pwqkv, g_wqkv);
    cudaGetSymbolAddress(&pwc1,  g_wc1);
    cudaGetSymbolAddress(&pwout, g_wout);
    cudaGetSymbolAddress(&pxh,   g_xh);
    cudaGetSymbolAddress(&patt,  g_att);
    cudaGetSymbolAddress(&pbn1h, g_bn1h);
    cudaGetSymbolAddress(&pc1,   g_c1);
    cudaGetSymbolAddress(&pst1,  g_st1);
    cudaGetSymbolAddress(&pst2,  g_st2);

    // pack weights + x to fp16
    pack_w_kernel<<<512, 256>>>(Wk, Wv, Wq, Wc1, Wout);
    pack_x_kernel<<<BATCH*128*(NQ/4)/256, 256>>>(x);

    // fused QKV projection (tensor cores) -> packed q/k/v
    gemm_h_kernel<<<dim3(NQ/256, 6, BATCH), 256>>>(
        (const uint32_t*)pwqkv, (const uint32_t*)pxh, nullptr, nullptr, 256, 256, 3);

    // flash attention (64q CTAs, 2/SM)
    cudaFuncSetAttribute((const void*)flash_h_kernel,
                         cudaFuncAttributeMaxDynamicSharedMemorySize, FSMEM);
    flash_h_kernel<<<dim3(NQ/64, BATCH), 128, FSMEM>>>();

    // conv1: Wc1 @ att -> g_c1 (fp32), then BN stats + BN/ReLU (packed out)
    gemm_h_kernel<<<dim3(NQ/256, 4, BATCH), 256>>>(
        (const uint32_t*)pwc1, (const uint32_t*)patt, nullptr, (float*)pc1, 128, 128, 0);
    stats_kernel<<<CPL, 256>>>((float*)pc1, (float2*)pst1, CPL);
    bn_relu_pack_kernel<<<BATCH*128*(NQ/4)/256, 256>>>((float*)pc1, (float2*)pst1,
                                                       gamma1, beta1);

    // out conv on concat [xh ; bn1h] -> d_out, then BN stats + BN/ReLU in place
    gemm_h_kernel<<<dim3(NQ/256, 4, BATCH), 256>>>(
        (const uint32_t*)pwout, (const uint32_t*)pxh, (const uint32_t*)pbn1h,
        out, 512, 256, 0);
    stats_kernel<<<CPL, 256>>>(out, (float2*)pst2, CPL);
    bn_relu_kernel<<<(BATCH*CPL*NQ/4)/256, 256>>>(out, out, (float2*)pst2,
                                                  gamma2, beta2, CPL);
}

// round 17
// speedup vs baseline: 1.2109x; 1.0937x over previous
#include <cuda_runtime.h>
#include <cuda_fp16.h>
#include <cstdint>

#define NQ   9216
#define CIN  128
#define CPL  256
#define BATCH 2

// ---------------- scratch (static device allocations, no cudaMalloc) ----------
__device__ uint32_t g_qh[BATCH*64*NQ];        // half2 (c,c+8 of 16-block), [b][p][n]
__device__ uint32_t g_kh[BATCH*64*NQ];        // same pairing as Q
__device__ uint32_t g_vh[BATCH*(NQ/2)*CIN];   // half2 (n,n+1) pairs, [b][npair][c]
__device__ uint32_t g_att[BATCH*64*NQ];       // attention out, half2 (c,c+1), [b][p][n]
__device__ uint32_t g_xh[BATCH*128*NQ];       // x packed, half2 (c,c+1), [b][p][n]
__device__ uint32_t g_c1h[BATCH*128*NQ];      // conv1 out, half2 (c,c+8 pairing), [b][pp][n]
__device__ uint32_t g_bn1h[BATCH*128*NQ];     // bn1 packed, same (c,c+8) pairing
__device__ uint32_t g_wqkv[384*128];          // rows 0-127 Wq(scaled),128-255 Wk,256-383 Wv
__device__ uint32_t g_wc1[256*64];
__device__ uint32_t g_wout[256*256];
__device__ float2   g_st1[CPL];
__device__ float2   g_st2[CPL];

__device__ __forceinline__ float fexp2(float x) {
    float y;
    asm("ex2.approx.ftz.f32 %0, %1;" : "=f"(y) : "f"(x));
    return y;
}
__device__ __forceinline__ void cpa16(uint32_t dst, const void* src) {
    asm volatile("cp.async.cg.shared.global [%0], [%1], 16;" :: "r"(dst), "l"(src));
}
__device__ __forceinline__ uint32_t h2u(__half2 h) { return *(uint32_t*)&h; }
__device__ __forceinline__ void mma_h(float* c,
    uint32_t a0, uint32_t a1, uint32_t a2, uint32_t a3, uint32_t b0, uint32_t b1) {
    asm volatile("mma.sync.aligned.m16n8k16.row.col.f32.f16.f16.f32 "
                 "{%0,%1,%2,%3}, {%4,%5,%6,%7}, {%8,%9}, {%0,%1,%2,%3};"
                 : "+f"(c[0]), "+f"(c[1]), "+f"(c[2]), "+f"(c[3])
                 : "r"(a0), "r"(a1), "r"(a2), "r"(a3), "r"(b0), "r"(b1));
}

// ---------------------------------------------------------------------------
// Packing kernels
// ---------------------------------------------------------------------------
__global__ void pack_w_kernel(const float* __restrict__ Wk, const float* __restrict__ Wv,
                              const float* __restrict__ Wq, const float* __restrict__ Wc1,
                              const float* __restrict__ Wout)
{
    int idx = blockIdx.x * 256 + threadIdx.x;
    if (idx < 384*128) {
        int r = idx >> 7, kp = idx & 127;
        const float* src; float s = 1.f;
        if (r < 128)      { src = Wq + (size_t)r*256;
                            s = 0.08838834764831845f * 1.4426950408889634f; }
        else if (r < 256) { src = Wk + (size_t)(r-128)*256; }
        else              { src = Wv + (size_t)(r-256)*256; }
        g_wqkv[idx] = h2u(__floats2half2_rn(src[2*kp]*s, src[2*kp+1]*s));
    } else if (idx < 384*128 + 256*64) {
        int i = idx - 384*128; int r = i >> 6, kp = i & 63;
        g_wc1[i] = h2u(__floats2half2_rn(Wc1[(size_t)r*128 + 2*kp],
                                         Wc1[(size_t)r*128 + 2*kp + 1]));
    } else if (idx < 384*128 + 256*64 + 256*256) {
        int i = idx - (384*128 + 256*64); int r = i >> 8, kp = i & 255;
        int ca, cb;
        if (kp < 128) { ca = 2*kp; cb = 2*kp + 1; }                 // x half: (c,c+1)
        else {                                                      // bn1 half: (c,c+8) perm
            int pp = kp - 128;
            ca = 256 + ((pp >> 3) << 4) + (pp & 7);
            cb = ca + 8;
        }
        g_wout[i] = h2u(__floats2half2_rn(Wout[(size_t)r*512 + ca],
                                          Wout[(size_t)r*512 + cb]));
    }
}

__global__ void pack_x_kernel(const float* __restrict__ x)
{
    int idx = blockIdx.x * 256 + threadIdx.x;    // BATCH*128*NQ/4 threads
    int n4 = (idx % (NQ/4)) * 4;
    int p  = (idx / (NQ/4)) % 128;
    int b  = idx / (128*(NQ/4));
    const float* r0 = x + ((size_t)b*256 + 2*p) * NQ + n4;
    const float* r1 = r0 + NQ;
    float4 v0 = *(const float4*)r0, v1 = *(const float4*)r1;
    uint4 o;
    o.x = h2u(__floats2half2_rn(v0.x, v1.x));
    o.y = h2u(__floats2half2_rn(v0.y, v1.y));
    o.z = h2u(__floats2half2_rn(v0.z, v1.z));
    o.w = h2u(__floats2half2_rn(v0.w, v1.w));
    *(uint4*)&g_xh[(size_t)b*128*NQ + (size_t)p*NQ + n4] = o;
}

// ---------------------------------------------------------------------------
// fp16 tensor-core GEMM: C[m][n] = sum_k W[m][k] * X[k][n]
// mode 0: fp32 out to Cf.  mode 3: fused QKV epilogues.  mode 4: half2
// (c,c+8)-paired output to g_c1h.
// ---------------------------------------------------------------------------
#define XSTR 264
#define WSTR 20

__global__ void __launch_bounds__(256) gemm_h_kernel(
    const uint32_t* __restrict__ Wh,
    const uint32_t* __restrict__ B1,
    const uint32_t* __restrict__ B2,
    float* __restrict__ Cf,
    int K, int K1, int mode)
{
    __shared__ uint32_t Xs[2][16*XSTR];
    __shared__ uint32_t Ws[2][64*WSTR];
    const uint32_t xsb = (uint32_t)__cvta_generic_to_shared(&Xs[0][0]);
    const uint32_t wsb = (uint32_t)__cvta_generic_to_shared(&Ws[0][0]);

    const int b = blockIdx.z;
    const int n0 = blockIdx.x * 256;
    const int y = blockIdx.y;
    const int m0 = y * 64;
    const int tid = threadIdx.x;
    const int lane = tid & 31, w = tid >> 5;
    const int mw = w & 3, nw = w >> 2;
    const int g = lane >> 2, t = lane & 3;
    const int Kh = K >> 1, K1h = K1 >> 1;
    const uint32_t* B1b = B1 + (size_t)b * K1h * NQ;
    const uint32_t* B2b = B2 ? (B2 + (size_t)b * (Kh - K1h) * NQ) : nullptr;
    const int nchunk = Kh / 16;

    {
        const uint32_t* src = B1b + n0;
        #pragma unroll
        for (int j = 0; j < 4; j++) {
            int idx = tid + j * 256;
            int r = idx >> 6, cu = (idx & 63) * 4;
            cpa16(xsb + (uint32_t)(r*XSTR + cu) * 4, src + (size_t)r * NQ + cu);
        }
        int rw = tid >> 2, cw = (tid & 3) * 4;
        cpa16(wsb + (uint32_t)(rw*WSTR + cw) * 4, Wh + (size_t)(m0 + rw) * Kh + cw);
    }
    asm volatile("cp.async.commit_group;");

    float acc[16][4];
    #pragma unroll
    for (int u = 0; u < 16; u++) { acc[u][0]=0; acc[u][1]=0; acc[u][2]=0; acc[u][3]=0; }

    for (int ch = 0; ch < nchunk; ch++) {
        const int buf = ch & 1;
        if (ch + 1 < nchunk) {
            int kp0 = (ch + 1) * 16;
            const uint32_t* src = (kp0 < K1h) ? (B1b + (size_t)kp0 * NQ + n0)
                                              : (B2b + (size_t)(kp0 - K1h) * NQ + n0);
            #pragma unroll
            for (int j = 0; j < 4; j++) {
                int idx = tid + j * 256;
                int r = idx >> 6, cu = (idx & 63) * 4;
                cpa16(xsb + (uint32_t)((buf^1)*16*XSTR + r*XSTR + cu) * 4,
                      src + (size_t)r * NQ + cu);
            }
            int rw = tid >> 2, cw = (tid & 3) * 4;
            cpa16(wsb + (uint32_t)((buf^1)*64*WSTR + rw*WSTR + cw) * 4,
                  Wh + (size_t)(m0 + rw) * Kh + kp0 + cw);
        }
        asm volatile("cp.async.commit_group;");
        asm volatile("cp.async.wait_group 1;");
        __syncthreads();

        const uint32_t* Xb = &Xs[buf][0];
        const uint32_t* Wb = &Ws[buf][0];
        #pragma unroll
        for (int j = 0; j < 2; j++) {
            uint32_t a0 = Wb[(mw*16+g)*WSTR   + 8*j + t];
            uint32_t a1 = Wb[(mw*16+g+8)*WSTR + 8*j + t];
            uint32_t a2 = Wb[(mw*16+g)*WSTR   + 8*j + 4 + t];
            uint32_t a3 = Wb[(mw*16+g+8)*WSTR + 8*j + 4 + t];
            #pragma unroll
            for (int u = 0; u < 16; u++) {
                uint32_t b0 = Xb[(8*j+t)*XSTR   + nw*128 + 8*u + g];
                uint32_t b1 = Xb[(8*j+4+t)*XSTR + nw*128 + 8*u + g];
                mma_h(acc[u], a0, a1, a2, a3, b0, b1);
            }
        }
        __syncthreads();
    }

    const int nb = n0 + nw*128 + 2*t;
    if (mode == 0) {
        float* Cb = Cf + ((size_t)b*256 + m0 + mw*16 + g) * NQ + nb;
        #pragma unroll
        for (int u = 0; u < 16; u++) {
            *(float2*)&Cb[8*u] = make_float2(acc[u][0], acc[u][1]);
            *(float2*)&Cb[(size_t)8*NQ + 8*u] = make_float2(acc[u][2], acc[u][3]);
        }
    } else if (mode == 4) {    // conv1 -> g_c1h, pairs (c, c+8)
        uint32_t* dst = g_c1h + (size_t)b*128*NQ + (size_t)(8*(y*4+mw)+g)*NQ + nb;
        #pragma unroll
        for (int u = 0; u < 16; u++) {
            uint2 v;
            v.x = h2u(__floats2half2_rn(acc[u][0], acc[u][2]));
            v.y = h2u(__floats2half2_rn(acc[u][1], acc[u][3]));
            *(uint2*)&dst[8*u] = v;
        }
    } else {
        if (y < 2) {           // Q -> g_qh, pairs (c, c+8)
            uint32_t* dst = g_qh + (size_t)b*64*NQ + (size_t)(8*(y*4+mw)+g)*NQ + nb;
            #pragma unroll
            for (int u = 0; u < 16; u++) {
                uint2 v;
                v.x = h2u(__floats2half2_rn(acc[u][0], acc[u][2]));
                v.y = h2u(__floats2half2_rn(acc[u][1], acc[u][3]));
                *(uint2*)&dst[8*u] = v;
            }
        } else if (y < 4) {    // K -> g_kh
            uint32_t* dst = g_kh + (size_t)b*64*NQ + (size_t)(8*((y-2)*4+mw)+g)*NQ + nb;
            #pragma unroll
            for (int u = 0; u < 16; u++) {
                uint2 v;
                v.x = h2u(__floats2half2_rn(acc[u][0], acc[u][2]));
                v.y = h2u(__floats2half2_rn(acc[u][1], acc[u][3]));
                *(uint2*)&dst[8*u] = v;
            }
        } else {               // V -> g_vh, pairs (n, n+1)
            uint32_t* dst = g_vh + (size_t)b*(NQ/2)*CIN;
            int c = (y-4)*64 + mw*16 + g;
            int npb = (n0 + nw*128)/2 + t;
            #pragma unroll
            for (int u = 0; u < 16; u++) {
                int np = npb + 4*u;
                dst[(size_t)np*CIN + c]     = h2u(__floats2half2_rn(acc[u][0], acc[u][1]));
                dst[(size_t)np*CIN + c + 8] = h2u(__floats2half2_rn(acc[u][2], acc[u][3]));
            }
        }
    }
}

// ---------------------------------------------------------------------------
// Flash attention, fp16 m16n8k16, no-rescale softmax (exact round-9 ordering:
// S -> softmax(l inline) -> PV).  K/V TRIPLE-buffered so the end-of-loop
// barrier is removed (prefetch at iter kt writes buf (kt+1)%3, last read at
// tile kt-2; skewed warps are safe).  CTA 64q x 4 warps, 2 CTAs/SM.
// ---------------------------------------------------------------------------
#define KSTH 72
#define VSTH 136
#define KWRD (64*KSTH)
#define VWRD (32*VSTH)
#define FSMEM ((3*KWRD + 3*VWRD) * 4)   // 107520 bytes

__global__ void __launch_bounds__(128, 2) flash_h_kernel()
{
    extern __shared__ float sm[];
    uint32_t* smu = (uint32_t*)sm;
    const uint32_t smb = (uint32_t)__cvta_generic_to_shared(sm);

    const int b  = blockIdx.y;
    const int q0 = blockIdx.x * 64;
    const int tid  = threadIdx.x;
    const int lane = tid & 31, w = tid >> 5;       // w in 0..3
    const int g = lane >> 2, t = lane & 3;

    const uint32_t* qhb = g_qh + (size_t)b * 64 * NQ;
    const uint32_t* khb = g_kh + (size_t)b * 64 * NQ;
    const uint32_t* vhb = g_vh + (size_t)b * (NQ/2) * CIN;

    // ---- stage Q (64 rows x 64 u32, stride KSTH; overlays K buffer 0) ----
    #pragma unroll
    for (int j = 0; j < 8; j++) {
        int idx = tid + j * 128;
        int p = idx >> 4, o4 = (idx & 15) * 4;
        cpa16(smb + (uint32_t)(p * KSTH + o4) * 4, qhb + (size_t)p * NQ + q0 + o4);
    }
    asm volatile("cp.async.commit_group;");
    asm volatile("cp.async.wait_group 0;");
    __syncthreads();

    const int ql = 16 * w + g;
    uint32_t qa[8][4];
    #pragma unroll
    for (int s = 0; s < 8; s++) {
        qa[s][0] = smu[(8*s + t)     * KSTH + ql];
        qa[s][1] = smu[(8*s + t)     * KSTH + ql + 8];
        qa[s][2] = smu[(8*s + 4 + t) * KSTH + ql];
        qa[s][3] = smu[(8*s + 4 + t) * KSTH + ql + 8];
    }
    __syncthreads();   // Q region now reusable as K buffer 0

    // ---- prologue: tile 0 K/V into buffer 0 ----
    #pragma unroll
    for (int j = 0; j < 8; j++) {
        int idx = tid + j * 128;
        int r = idx >> 4, ch = (idx & 15) * 4;
        cpa16(smb + (uint32_t)(r * KSTH + ch) * 4, khb + (size_t)r * NQ + ch);
    }
    #pragma unroll
    for (int j = 0; j < 8; j++) {
        int idx = tid + j * 128;
        int r = idx >> 5, ch = (idx & 31) * 4;
        cpa16(smb + (uint32_t)(3*KWRD + r * VSTH + ch) * 4, vhb + (size_t)r * CIN + ch);
    }
    asm volatile("cp.async.commit_group;");

    float o_[16][4];
    #pragma unroll
    for (int n = 0; n < 16; n++) { o_[n][0]=0; o_[n][1]=0; o_[n][2]=0; o_[n][3]=0; }
    float l0 = 0.f, l1 = 0.f;

    int cb = 0;
    for (int kt = 0; kt < NQ/64; kt++) {
        int nbuf = cb + 1; if (nbuf == 3) nbuf = 0;
        if (kt + 1 < NQ/64) {
            const int k0n  = (kt + 1) * 64;
            const int kp0n = (kt + 1) * 32;
            #pragma unroll
            for (int j = 0; j < 8; j++) {
                int idx = tid + j * 128;
                int r = idx >> 4, ch = (idx & 15) * 4;
                cpa16(smb + (uint32_t)(nbuf*KWRD + r * KSTH + ch) * 4,
                      khb + (size_t)r * NQ + k0n + ch);
            }
            #pragma unroll
            for (int j = 0; j < 8; j++) {
                int idx = tid + j * 128;
                int r = idx >> 5, ch = (idx & 31) * 4;
                cpa16(smb + (uint32_t)(3*KWRD + nbuf*VWRD + r * VSTH + ch) * 4,
                      vhb + (size_t)(kp0n + r) * CIN + ch);
            }
        }
        asm volatile("cp.async.commit_group;");
        asm volatile("cp.async.wait_group 1;");
        __syncthreads();           // tile kt visible to all warps

        const uint32_t* Kp = smu + cb * KWRD;
        const uint32_t* Vp = smu + 3*KWRD + cb * VWRD;

        // ---- S = Q^T K ----
        float sc[8][4];
        #pragma unroll
        for (int u = 0; u < 8; u++) { sc[u][0]=0; sc[u][1]=0; sc[u][2]=0; sc[u][3]=0; }
        #pragma unroll
        for (int s = 0; s < 8; s++) {
            const uint32_t* kr0 = Kp + (8*s + t) * KSTH + g;
            const uint32_t* kr1 = kr0 + 4 * KSTH;
            #pragma unroll
            for (int u = 0; u < 8; u++)
                mma_h(sc[u], qa[s][0], qa[s][1], qa[s][2], qa[s][3],
                      kr0[8*u], kr1[8*u]);
        }

        // ---- no-rescale softmax: P = 2^s, per-thread l partials ----
        uint32_t pb[8][2];
        #pragma unroll
        for (int u = 0; u < 8; u++) {
            float e0 = fexp2(sc[u][0]);
            float e1 = fexp2(sc[u][1]);
            float e2 = fexp2(sc[u][2]);
            float e3 = fexp2(sc[u][3]);
            l0 += e0 + e1;
            l1 += e2 + e3;
            pb[u][0] = h2u(__floats2half2_rn(e0, e1));
            pb[u][1] = h2u(__floats2half2_rn(e2, e3));
        }

        // ---- O += P V^T ----
        #pragma unroll
        for (int nb2 = 0; nb2 < 16; nb2++) {
            #pragma unroll
            for (int s = 0; s < 4; s++) {
                uint32_t b0 = Vp[(8*s + t)     * VSTH + 8*nb2 + g];
                uint32_t b1 = Vp[(8*s + 4 + t) * VSTH + 8*nb2 + g];
                mma_h(o_[nb2], pb[2*s][0], pb[2*s][1], pb[2*s+1][0], pb[2*s+1][1],
                      b0, b1);
            }
        }
        cb = nbuf;                 // no end barrier: triple buffering keeps it safe
    }

    // ---- epilogue: reduce l across quad, normalize, pack, store ----
    l0 += __shfl_xor_sync(0xffffffffu, l0, 1);
    l0 += __shfl_xor_sync(0xffffffffu, l0, 2);
    l1 += __shfl_xor_sync(0xffffffffu, l1, 1);
    l1 += __shfl_xor_sync(0xffffffffu, l1, 2);
    const float i0 = 1.f / l0, i1 = 1.f / l1;
    uint32_t* op = g_att + (size_t)b * 64 * NQ;
    const int qA = q0 + 16*w + g, qB = qA + 8;
    #pragma unroll
    for (int nb2 = 0; nb2 < 16; nb2++) {
        int p = 4*nb2 + t;
        op[(size_t)p * NQ + qA] = h2u(__floats2half2_rn(o_[nb2][0]*i0, o_[nb2][1]*i0));
        op[(size_t)p * NQ + qB] = h2u(__floats2half2_rn(o_[nb2][2]*i1, o_[nb2][3]*i1));
    }
}

// ---------------------------------------------------------------------------
// BN statistics + BN/ReLU epilogues
// ---------------------------------------------------------------------------
// stats over half2 (c,c+8)-paired buffer: one block per pair row pp.
__global__ void stats_h_kernel(const uint32_t* __restrict__ buf, float2* __restrict__ st)
{
    const int pp = blockIdx.x, tid = threadIdx.x;
    const int c0 = ((pp >> 3) << 4) + (pp & 7);
    float s1l = 0.f, s2l = 0.f, s1h = 0.f, s2h = 0.f;
    for (int b = 0; b < BATCH; b++) {
        const uint32_t* p = buf + ((size_t)b*128 + pp) * NQ;
        for (int n = tid * 4; n < NQ; n += 1024) {
            uint4 v = *(const uint4*)(p + n);
            float2 f0 = __half22float2(*(__half2*)&v.x);
            float2 f1 = __half22float2(*(__half2*)&v.y);
            float2 f2 = __half22float2(*(__half2*)&v.z);
            float2 f3 = __half22float2(*(__half2*)&v.w);
            s1l += f0.x + f1.x + f2.x + f3.x;
            s2l += f0.x*f0.x + f1.x*f1.x + f2.x*f2.x + f3.x*f3.x;
            s1h += f0.y + f1.y + f2.y + f3.y;
            s2h += f0.y*f0.y + f1.y*f1.y + f2.y*f2.y + f3.y*f3.y;
        }
    }
    __shared__ float sh[4][256];
    sh[0][tid] = s1l; sh[1][tid] = s2l; sh[2][tid] = s1h; sh[3][tid] = s2h;
    __syncthreads();
    for (int o = 128; o; o >>= 1) {
        if (tid < o) {
            sh[0][tid] += sh[0][tid+o]; sh[1][tid] += sh[1][tid+o];
            sh[2][tid] += sh[2][tid+o]; sh[3][tid] += sh[3][tid+o];
        }
        __syncthreads();
    }
    if (tid == 0) {
        float invn = 1.f / (float)(BATCH * NQ);
        float ml = sh[0][0] * invn, vl = sh[1][0] * invn - ml*ml;
        float mh = sh[2][0] * invn, vh = sh[3][0] * invn - mh*mh;
        st[c0]     = make_float2(ml, rsqrtf(vl + 1e-5f));
        st[c0 + 8] = make_float2(mh, rsqrtf(vh + 1e-5f));
    }
}

// BN+ReLU on g_c1h (half2 (c,c+8) pairs) -> g_bn1h (same layout)
__global__ void bn_relu_pack_h_kernel(const uint32_t* __restrict__ in,
                                      const float2* __restrict__ st,
                                      const float* __restrict__ gamma,
                                      const float* __restrict__ beta)
{
    int idx = blockIdx.x * 256 + threadIdx.x;     // BATCH*128*NQ/4
    int n4 = (idx % (NQ/4)) * 4;
    int pp = (idx / (NQ/4)) % 128;
    int b  = idx / (128*(NQ/4));
    int c0 = ((pp >> 3) << 4) + (pp & 7), c1 = c0 + 8;
    float2 sA = st[c0], sB = st[c1];
    float gA = gamma[c0] * sA.y, bA = beta[c0] - sA.x * gA;
    float gB = gamma[c1] * sB.y, bB = beta[c1] - sB.x * gB;
    uint4 v = *(const uint4*)(in + ((size_t)b*128 + pp) * NQ + n4);
    uint32_t* vp = &v.x;
    uint4 o;
    uint32_t* op = &o.x;
    #pragma unroll
    for (int i = 0; i < 4; i++) {
        float2 f = __half22float2(*(__half2*)&vp[i]);
        f.x = fmaxf(f.x * gA + bA, 0.f);
        f.y = fmaxf(f.y * gB + bB, 0.f);
        op[i] = h2u(__floats2half2_rn(f.x, f.y));
    }
    *(uint4*)&g_bn1h[((size_t)b*128 + pp) * NQ + n4] = o;
}

// fp32 stats for the final output
__global__ void stats_kernel(const float* __restrict__ buf, float2* __restrict__ st, int C)
{
    const int ch = blockIdx.x, tid = threadIdx.x;
    float s1 = 0.f, s2 = 0.f;
    for (int b = 0; b < BATCH; b++) {
        const float* p = buf + ((size_t)b * C + ch) * NQ;
        for (int n = tid * 4; n < NQ; n += 1024) {
            float4 t = *(const float4*)(p + n);
            s1 += t.x + t.y + t.z + t.w;
            s2 += t.x*t.x + t.y*t.y + t.z*t.z + t.w*t.w;
        }
    }
    __shared__ float sh1[256], sh2[256];
    sh1[tid] = s1; sh2[tid] = s2;
    __syncthreads();
    for (int o = 128; o; o >>= 1) {
        if (tid < o) { sh1[tid] += sh1[tid + o]; sh2[tid] += sh2[tid + o]; }
        __syncthreads();
    }
    if (tid == 0) {
        float invn = 1.f / (float)(BATCH * NQ);
        float mean = sh1[0] * invn;
        float var  = sh2[0] * invn - mean * mean;
        st[ch] = make_float2(mean, rsqrtf(var + 1e-5f));
    }
}

__global__ void bn_relu_kernel(const float* __restrict__ in, float* __restrict__ out,
                               const float2* __restrict__ st,
                               const float* __restrict__ gamma,
                               const float* __restrict__ beta, int C)
{
    size_t idx = (size_t)blockIdx.x * blockDim.x + threadIdx.x;
    size_t fi = idx * 4;
    int ch = (int)((fi / NQ) % C);
    float2 s = st[ch];
    float g  = gamma[ch] * s.y;
    float bb = beta[ch] - s.x * g;
    float4 t = *(const float4*)(in + fi);
    t.x = fmaxf(t.x * g + bb, 0.f);
    t.y = fmaxf(t.y * g + bb, 0.f);
    t.z = fmaxf(t.z * g + bb, 0.f);
    t.w = fmaxf(t.w * g + bb, 0.f);
    *(float4*)(out + fi) = t;
}

// ---------------------------------------------------------------------------
extern "C" void kernel_launch(void* const* d_in, const int* in_sizes, int n_in,
                              void* d_out, int out_size)
{
    const float* x      = (const float*)d_in[0];
    const float* Wk     = (const float*)d_in[1];
    const float* Wv     = (const float*)d_in[2];
    const float* Wq     = (const float*)d_in[3];
    const float* Wc1    = (const float*)d_in[4];
    const float* gamma1 = (const float*)d_in[5];
    const float* beta1  = (const float*)d_in[6];
    const float* Wout   = (const float*)d_in[7];
    const float* gamma2 = (const float*)d_in[8];
    const float* beta2  = (const float*)d_in[9];
    float* out = (float*)d_out;

    void *pwqkv, *pwc1, *pwout, *pxh, *patt, *pc1h, *pbn1h, *pst1, *pst2;
    cudaGetSymbolAddress(&pwqkv, g_wqkv);
    cudaGetSymbolAddress(&pwc1,  g_wc1);
    cudaGetSymbolAddress(&pwout, g_wout);
    cudaGetSymbolAddress(&pxh,   g_xh);
    cudaGetSymbolAddress(&patt,  g_att);
    cudaGetSymbolAddress(&pc1h,  g_c1h);
    cudaGetSymbolAddress(&pbn1h, g_bn1h);
    cudaGetSymbolAddress(&pst1,  g_st1);
    cudaGetSymbolAddress(&pst2,  g_st2);

    // pack weights + x to fp16
    pack_w_kernel<<<512, 256>>>(Wk, Wv, Wq, Wc1, Wout);
    pack_x_kernel<<<BATCH*128*(NQ/4)/256, 256>>>(x);

    // fused QKV projection (tensor cores) -> packed q/k/v
    gemm_h_kernel<<<dim3(NQ/256, 6, BATCH), 256>>>(
        (const uint32_t*)pwqkv, (const uint32_t*)pxh, nullptr, nullptr, 256, 256, 3);

    // flash attention (64q CTAs, 2/SM, triple-buffered single-barrier loop)
    cudaFuncSetAttribute((const void*)flash_h_kernel,
                         cudaFuncAttributeMaxDynamicSharedMemorySize, FSMEM);
    flash_h_kernel<<<dim3(NQ/64, BATCH), 128, FSMEM>>>();

    // conv1: Wc1 @ att -> g_c1h (fp16 pairs), then BN stats + BN/ReLU (half chain)
    gemm_h_kernel<<<dim3(NQ/256, 4, BATCH), 256>>>(
        (const uint32_t*)pwc1, (const uint32_t*)patt, nullptr, nullptr, 128, 128, 4);
    stats_h_kernel<<<128, 256>>>((const uint32_t*)pc1h, (float2*)pst1);
    bn_relu_pack_h_kernel<<<BATCH*128*(NQ/4)/256, 256>>>((const uint32_t*)pc1h,
                                                         (float2*)pst1, gamma1, beta1);

    // out conv on concat [xh ; bn1h] -> d_out, then BN stats + BN/ReLU in place
    gemm_h_kernel<<<dim3(NQ/256, 4, BATCH), 256>>>(
        (const uint32_t*)pwout, (const uint32_t*)pxh, (const uint32_t*)pbn1h,
        out, 512, 256, 0);
    stats_kernel<<<CPL, 256>>>(out, (float2*)pst2, CPL);
    bn_relu_kernel<<<(BATCH*CPL*NQ/4)/256, 256>>>(out, out, (float2*)pst2,
                                                  gamma2, beta2, CPL);
}